// round 3
// baseline (speedup 1.0000x reference)
#include <cuda_runtime.h>

// FixBatchChebConv: B=8, N=50000, Cin=Cout=64, K=3, E=400000
#define BB    8
#define NN    50000
#define CC    64
#define KORD  3
#define EE    400000
#define FF    512           // BB*CC, features per node in transposed layout
#define FF4   (FF/4)

#define ASTR  68            // padded shared stride for A tile chunk (64 x 64)

// ---------------- scratch (static device globals; no runtime allocation) ----
__device__ float g_xt[(size_t)NN * FF];   // x transposed  [N,512]
__device__ float g_t1[(size_t)NN * FF];   // tx1 = L @ x
__device__ float g_t2[(size_t)NN * FF];   // tx2 = 2 L tx1 - x
__device__ int   g_deg[NN];
__device__ int   g_rowstart[NN];
__device__ int   g_fill[NN];
__device__ float g_dinv[NN];
__device__ int   g_col[EE];
__device__ float g_lap[EE];
__device__ int   g_total;
__device__ int   g_is64;

// ---------------- setup kernels --------------------------------------------
__global__ void k_init() {
    int n = blockIdx.x * blockDim.x + threadIdx.x;
    if (n < NN) { g_deg[n] = 0; g_fill[n] = 0; }
    if (n == 0) g_total = 0;
}

// Detect whether edge_index is int64 or int32 (JAX may silently downcast).
// If the data is int32, reading it as int64 packs two random indices per word,
// making the value >= NN almost surely for at least one of 64 samples.
__global__ void k_detect(const void* ei) {
    const long long* p = (const long long*)ei;
    int lane = threadIdx.x;           // 64 threads
    long long v = p[lane];
    int ok = (v >= 0 && v < NN) ? 1 : 0;
    __syncthreads();
    unsigned m0 = __ballot_sync(0xffffffffu, ok);
    __shared__ unsigned warp_ok[2];
    if ((lane & 31) == 0) warp_ok[lane >> 5] = m0;
    __syncthreads();
    if (lane == 0) g_is64 = (warp_ok[0] == 0xffffffffu && warp_ok[1] == 0xffffffffu) ? 1 : 0;
}

__device__ __forceinline__ void load_edge(const void* ei, int e, int& r, int& c) {
    if (g_is64) {
        const long long* p = (const long long*)ei;
        r = (int)p[e]; c = (int)p[EE + e];
    } else {
        const int* p = (const int*)ei;
        r = p[e]; c = p[EE + e];
    }
}

__global__ void k_count(const void* ei) {
    int e = blockIdx.x * blockDim.x + threadIdx.x;
    if (e >= EE) return;
    int r, c; load_edge(ei, e, r, c);
    if (r != c) atomicAdd(&g_deg[r], 1);
}

__global__ void k_dinv() {
    int n = blockIdx.x * blockDim.x + threadIdx.x;
    if (n >= NN) return;
    int d = g_deg[n];
    g_dinv[n] = (d > 0) ? rsqrtf((float)d) : 0.0f;
}

// Assign each row a contiguous CSR segment (warp-aggregated atomic offset).
__global__ void k_assign() {
    int n = blockIdx.x * blockDim.x + threadIdx.x;
    int lane = threadIdx.x & 31;
    int d = (n < NN) ? g_deg[n] : 0;
    int incl = d;
    #pragma unroll
    for (int o = 1; o < 32; o <<= 1) {
        int y = __shfl_up_sync(0xffffffffu, incl, o);
        if (lane >= o) incl += y;
    }
    int tot = __shfl_sync(0xffffffffu, incl, 31);
    int base = 0;
    if (lane == 0) base = atomicAdd(&g_total, tot);
    base = __shfl_sync(0xffffffffu, base, 0);
    if (n < NN) g_rowstart[n] = base + incl - d;
}

__global__ void k_fill(const void* ei) {
    int e = blockIdx.x * blockDim.x + threadIdx.x;
    if (e >= EE) return;
    int r, c; load_edge(ei, e, r, c);
    if (r != c) {
        int pos = atomicAdd(&g_fill[r], 1);
        int idx = g_rowstart[r] + pos;
        g_col[idx] = c;
        g_lap[idx] = -g_dinv[r] * g_dinv[c];
    }
}

// xt[n][b*64+c] = x[b][n][c], float4-vectorized on both sides.
__global__ void k_transpose(const float* __restrict__ x) {
    int gid = blockIdx.x * blockDim.x + threadIdx.x;   // over NN*FF/4
    if (gid >= NN * FF4) return;
    int c4 = gid & 15;
    int b  = (gid >> 4) & 7;
    int n  = gid >> 7;
    float4 v = ((const float4*)x)[((size_t)b * NN + n) * 16 + c4];
    ((float4*)g_xt)[gid] = v;
}

// One warp per row: dst[r] = alpha * sum_e lap[e]*src[col[e]] (- xt[r] on pass 1).
// pass 0: t1 = L @ xt ;  pass 1: t2 = 2*(L @ t1) - xt
__global__ void k_spmm(int pass) {
    int gw   = (blockIdx.x * blockDim.x + threadIdx.x) >> 5;
    int lane = threadIdx.x & 31;
    if (gw >= NN) return;

    const float* src  = (pass == 0) ? g_xt : g_t1;
    float*       dst  = (pass == 0) ? g_t1 : g_t2;

    int s = g_rowstart[gw];
    int e = s + g_deg[gw];

    float4 acc[4];
    #pragma unroll
    for (int q = 0; q < 4; q++) acc[q] = make_float4(0.f, 0.f, 0.f, 0.f);

    const float4* srcv = (const float4*)src;
    for (int i = s; i < e; i++) {
        int   c = g_col[i];
        float w = g_lap[i];
        size_t b0 = (size_t)c * FF4 + lane;
        #pragma unroll
        for (int q = 0; q < 4; q++) {
            float4 v = __ldg(&srcv[b0 + q * 32]);
            acc[q].x += w * v.x; acc[q].y += w * v.y;
            acc[q].z += w * v.z; acc[q].w += w * v.w;
        }
    }

    size_t o0 = (size_t)gw * FF4 + lane;
    float4* dstv = (float4*)dst;
    if (pass == 0) {
        #pragma unroll
        for (int q = 0; q < 4; q++) dstv[o0 + q * 32] = acc[q];
    } else {
        const float4* cv = (const float4*)g_xt;
        #pragma unroll
        for (int q = 0; q < 4; q++) {
            float4 c0 = __ldg(&cv[o0 + q * 32]);
            float4 o;
            o.x = 2.0f * acc[q].x - c0.x;
            o.y = 2.0f * acc[q].y - c0.y;
            o.z = 2.0f * acc[q].z - c0.z;
            o.w = 2.0f * acc[q].w - c0.w;
            dstv[o0 + q * 32] = o;
        }
    }
}

// Fused epilogue GEMM: out[b,n,co] = bias[co]
//   + sum_t sum_ci buf_t[n][b*64+ci] * W[t][ci][co]
// Block: 8 nodes -> 64 (n,b) rows x 64 cols. Loops over the 3 taps, staging
// a 64x64 W chunk (16KB) + 64x68-padded A chunk (17KB) in STATIC shared
// memory (33.8KB < 48KB default -> no cudaFuncSetAttribute needed).
// 256 threads, 4x4 microtile: 2x LDS.128 + 16 FFMA per k.
__global__ void __launch_bounds__(256) k_gemm(const float* __restrict__ wgt,
                                              const float* __restrict__ bias,
                                              float* __restrict__ out) {
    __shared__ float Ws[64 * 64];      // W[t] chunk, [ci][co]
    __shared__ float As[64 * ASTR];    // A chunk, [ci][dn*8+b]

    int tid = threadIdx.x;
    int n0  = blockIdx.x * 8;

    int mr = (tid & 15) << 2;
    int cr = (tid >> 4) << 2;

    float acc[4][4] = {};

    #pragma unroll
    for (int t = 0; t < 3; t++) {
        const float* src = (t == 0) ? g_xt : (t == 1) ? g_t1 : g_t2;

        if (t) __syncthreads();        // protect previous-tap reads

        // W chunk: straight 4096-float copy (W[t][ci][co] == Ws[ci*64+co])
        {
            const float4* wv  = (const float4*)(wgt + t * 4096);
            float4*       wsv = (float4*)Ws;
            #pragma unroll
            for (int i = 0; i < 4; i++) wsv[tid + i * 256] = wv[tid + i * 256];
        }
        // A chunk: As[ci][dn*8+b] = src[(n0+dn)*512 + b*64+ci]
        #pragma unroll
        for (int i = 0; i < 16; i++) {
            int idx = tid + i * 256;   // 8 * 512 = 4096 elems
            int dn  = idx >> 9;
            int j   = idx & 511;
            int ci  = j & 63;
            int b   = j >> 6;
            As[ci * ASTR + dn * 8 + b] = src[(size_t)(n0 + dn) * FF + j];
        }
        __syncthreads();

        #pragma unroll 4
        for (int kk = 0; kk < 64; kk++) {
            float4 av = *(const float4*)(As + kk * ASTR + mr);
            float4 wv = *(const float4*)(Ws + (kk << 6) + cr);
            acc[0][0] += av.x * wv.x; acc[0][1] += av.x * wv.y; acc[0][2] += av.x * wv.z; acc[0][3] += av.x * wv.w;
            acc[1][0] += av.y * wv.x; acc[1][1] += av.y * wv.y; acc[1][2] += av.y * wv.z; acc[1][3] += av.y * wv.w;
            acc[2][0] += av.z * wv.x; acc[2][1] += av.z * wv.y; acc[2][2] += av.z * wv.z; acc[2][3] += av.z * wv.w;
            acc[3][0] += av.w * wv.x; acc[3][1] += av.w * wv.y; acc[3][2] += av.w * wv.z; acc[3][3] += av.w * wv.w;
        }
    }

    float4 bv = *(const float4*)(bias + cr);
    #pragma unroll
    for (int r = 0; r < 4; r++) {
        int m  = mr + r;
        int dn = m >> 3;
        int b  = m & 7;
        float4 o;
        o.x = acc[r][0] + bv.x;
        o.y = acc[r][1] + bv.y;
        o.z = acc[r][2] + bv.z;
        o.w = acc[r][3] + bv.w;
        *(float4*)(out + ((size_t)b * NN + (n0 + dn)) * 64 + cr) = o;
    }
}

// ---------------- launch ----------------------------------------------------
extern "C" void kernel_launch(void* const* d_in, const int* in_sizes, int n_in,
                              void* d_out, int out_size) {
    const float* x    = (const float*)d_in[0];   // [8, 50000, 64] f32
    const float* wgt  = (const float*)d_in[1];   // [3, 64, 64]    f32
    const float* bias = (const float*)d_in[2];   // [64]           f32
    const void*  ei   = d_in[3];                 // [2, 400000] int64 or int32
    float* out = (float*)d_out;                  // [8, 50000, 64] f32

    k_init<<<(NN + 255) / 256, 256>>>();
    k_detect<<<1, 64>>>(ei);
    k_count<<<(EE + 255) / 256, 256>>>(ei);
    k_dinv<<<(NN + 255) / 256, 256>>>();
    k_assign<<<(NN + 255) / 256, 256>>>();
    k_fill<<<(EE + 255) / 256, 256>>>(ei);
    k_transpose<<<(NN * FF4 + 255) / 256, 256>>>(x);
    k_spmm<<<(NN * 32 + 255) / 256, 256>>>(0);
    k_spmm<<<(NN * 32 + 255) / 256, 256>>>(1);
    k_gemm<<<NN / 8, 256>>>(wgt, bias, out);
}

// round 5
// speedup vs baseline: 1.1345x; 1.1345x over previous
#include <cuda_runtime.h>

// FixBatchChebConv: B=8, N=50000, Cin=Cout=64, K=3, E=400000
#define BB    8
#define NN    50000
#define CC    64
#define KORD  3
#define EE    400000
#define FF    512           // BB*CC, features per node in transposed layout
#define FF4   (FF/4)

// ---------------- scratch (static device globals; no runtime allocation) ----
__device__ float g_xt[(size_t)NN * FF];   // x transposed  [N,512]
__device__ float g_t1[(size_t)NN * FF];   // tx1 = L @ x
__device__ float g_t2[(size_t)NN * FF];   // tx2 = 2 L tx1 - x
__device__ int   g_deg[NN];
__device__ int   g_rowstart[NN];
__device__ int   g_fill[NN];
__device__ float g_dinv[NN];
__device__ int   g_col[EE];
__device__ float g_lap[EE];
__device__ int   g_total;
__device__ int   g_is64;

// ---------------- setup kernels --------------------------------------------
__global__ void k_init() {
    int n = blockIdx.x * blockDim.x + threadIdx.x;
    if (n < NN) { g_deg[n] = 0; g_fill[n] = 0; }
    if (n == 0) g_total = 0;
}

// Detect whether edge_index is int64 or int32 (JAX may silently downcast).
__global__ void k_detect(const void* ei) {
    const long long* p = (const long long*)ei;
    int lane = threadIdx.x;           // 64 threads
    long long v = p[lane];
    int ok = (v >= 0 && v < NN) ? 1 : 0;
    __syncthreads();
    unsigned m0 = __ballot_sync(0xffffffffu, ok);
    __shared__ unsigned warp_ok[2];
    if ((lane & 31) == 0) warp_ok[lane >> 5] = m0;
    __syncthreads();
    if (lane == 0) g_is64 = (warp_ok[0] == 0xffffffffu && warp_ok[1] == 0xffffffffu) ? 1 : 0;
}

__device__ __forceinline__ void load_edge(const void* ei, int e, int& r, int& c) {
    if (g_is64) {
        const long long* p = (const long long*)ei;
        r = (int)p[e]; c = (int)p[EE + e];
    } else {
        const int* p = (const int*)ei;
        r = p[e]; c = p[EE + e];
    }
}

__global__ void k_count(const void* ei) {
    int e = blockIdx.x * blockDim.x + threadIdx.x;
    if (e >= EE) return;
    int r, c; load_edge(ei, e, r, c);
    if (r != c) atomicAdd(&g_deg[r], 1);
}

__global__ void k_dinv() {
    int n = blockIdx.x * blockDim.x + threadIdx.x;
    if (n >= NN) return;
    int d = g_deg[n];
    g_dinv[n] = (d > 0) ? rsqrtf((float)d) : 0.0f;
}

// Assign each row a contiguous CSR segment (warp-aggregated atomic offset).
__global__ void k_assign() {
    int n = blockIdx.x * blockDim.x + threadIdx.x;
    int lane = threadIdx.x & 31;
    int d = (n < NN) ? g_deg[n] : 0;
    int incl = d;
    #pragma unroll
    for (int o = 1; o < 32; o <<= 1) {
        int y = __shfl_up_sync(0xffffffffu, incl, o);
        if (lane >= o) incl += y;
    }
    int tot = __shfl_sync(0xffffffffu, incl, 31);
    int base = 0;
    if (lane == 0) base = atomicAdd(&g_total, tot);
    base = __shfl_sync(0xffffffffu, base, 0);
    if (n < NN) g_rowstart[n] = base + incl - d;
}

__global__ void k_fill(const void* ei) {
    int e = blockIdx.x * blockDim.x + threadIdx.x;
    if (e >= EE) return;
    int r, c; load_edge(ei, e, r, c);
    if (r != c) {
        int pos = atomicAdd(&g_fill[r], 1);
        int idx = g_rowstart[r] + pos;
        g_col[idx] = c;
        g_lap[idx] = -g_dinv[r] * g_dinv[c];
    }
}

// xt[n][b*64+c] = x[b][n][c], float4-vectorized on both sides.
__global__ void k_transpose(const float* __restrict__ x) {
    int gid = blockIdx.x * blockDim.x + threadIdx.x;   // over NN*FF/4
    if (gid >= NN * FF4) return;
    int c4 = gid & 15;
    int b  = (gid >> 4) & 7;
    int n  = gid >> 7;
    float4 v = ((const float4*)x)[((size_t)b * NN + n) * 16 + c4];
    ((float4*)g_xt)[gid] = v;
}

// One warp per row. pass 0: t1 = L @ xt ; pass 1: t2 = 2*(L @ t1) - xt
__global__ void k_spmm(int pass) {
    int gw   = (blockIdx.x * blockDim.x + threadIdx.x) >> 5;
    int lane = threadIdx.x & 31;
    if (gw >= NN) return;

    const float* src = (pass == 0) ? g_xt : g_t1;
    float*       dst = (pass == 0) ? g_t1 : g_t2;

    int s = g_rowstart[gw];
    int e = s + g_deg[gw];

    float4 acc[4];
    #pragma unroll
    for (int q = 0; q < 4; q++) acc[q] = make_float4(0.f, 0.f, 0.f, 0.f);

    const float4* srcv = (const float4*)src;
    for (int i = s; i < e; i++) {
        int   c = g_col[i];
        float w = g_lap[i];
        size_t b0 = (size_t)c * FF4 + lane;
        #pragma unroll
        for (int q = 0; q < 4; q++) {
            float4 v = __ldg(&srcv[b0 + q * 32]);
            acc[q].x += w * v.x; acc[q].y += w * v.y;
            acc[q].z += w * v.z; acc[q].w += w * v.w;
        }
    }

    size_t o0 = (size_t)gw * FF4 + lane;
    float4* dstv = (float4*)dst;
    if (pass == 0) {
        #pragma unroll
        for (int q = 0; q < 4; q++) dstv[o0 + q * 32] = acc[q];
    } else {
        const float4* cv = (const float4*)g_xt;
        #pragma unroll
        for (int q = 0; q < 4; q++) {
            float4 c0 = __ldg(&cv[o0 + q * 32]);
            float4 o;
            o.x = 2.0f * acc[q].x - c0.x;
            o.y = 2.0f * acc[q].y - c0.y;
            o.z = 2.0f * acc[q].z - c0.z;
            o.w = 2.0f * acc[q].w - c0.w;
            dstv[o0 + q * 32] = o;
        }
    }
}

// ---------------- packed f32x2 helpers --------------------------------------
__device__ __forceinline__ unsigned long long pack2(float f) {
    unsigned long long d;
    unsigned u = __float_as_uint(f);
    asm("mov.b64 %0, {%1, %1};" : "=l"(d) : "r"(u));
    return d;
}
__device__ __forceinline__ void unpack2(unsigned long long v, float& lo, float& hi) {
    unsigned a, b;
    asm("mov.b64 {%0, %1}, %2;" : "=r"(a), "=r"(b) : "l"(v));
    lo = __uint_as_float(a); hi = __uint_as_float(b);
}
#define FMA2(acc, a, b) asm("fma.rn.f32x2 %0, %1, %2, %0;" : "+l"(acc) : "l"(a), "l"(b))

// Fused epilogue GEMM with packed f32x2 FFMA2 (2 MACs per fma-pipe slot):
//   out[b,n,co] = bias[co] + sum_t sum_ci buf_t[n][b*64+ci] * W[t][ci][co]
// Block tile: 256 rows (32 nodes x 8 batches) x 64 cols; K=192 in 6 chunks of 32.
// 256 threads = 8 warps; warp w owns cols [8w, 8w+8) -> W reads are warp-uniform
// broadcasts. Thread microtile 8 rows x 8 cols as 4 row-PAIRS (LDS.64 -> packed
// f32x2) x 8 dup'd weights: 32 FFMA2 per k per thread, fma-pipe bound at the
// doubled 128 MAC/cyc/SM rate.
#define KC    32
#define AST   258            // even (LDS.64-aligned pairs), 2-way STS conflict only
__global__ void __launch_bounds__(256, 2) k_gemm2(const float* __restrict__ wgt,
                                                   const float* __restrict__ bias,
                                                   float* __restrict__ out) {
    __shared__ float As[KC * AST];   // [k][m], m = dn*8+b     (33024 B)
    __shared__ float Ws[KC * 64];    // [k][co]                ( 8192 B)

    int tid = threadIdx.x;
    int tx  = tid & 31;
    int wp  = tid >> 5;              // col group: cols wp*8 .. wp*8+7
    int n0  = blockIdx.x * 32;

    int s_ci = tid & 31;             // staging: k within chunk
    int s_b  = tid >> 5;             // staging: batch

    unsigned long long acc[4][8];
    #pragma unroll
    for (int i = 0; i < 4; i++)
        #pragma unroll
        for (int j = 0; j < 8; j++) acc[i][j] = 0ULL;

    #pragma unroll 1
    for (int kc = 0; kc < 6; kc++) {
        int t    = kc >> 1;
        int koff = (kc & 1) * 32;
        const float* src = (t == 0) ? g_xt : (t == 1) ? g_t1 : g_t2;

        if (kc) __syncthreads();

        // stage W chunk: Ws[kk*64+co] = wgt[t*4096 + (koff+kk)*64 + co] (linear)
        #pragma unroll
        for (int i = 0; i < 8; i++) {
            int j = tid + i * 256;
            Ws[j] = __ldg(&wgt[t * 4096 + koff * 64 + j]);
        }
        // stage A chunk: As[ci][dn*8+b] = src[(n0+dn)*512 + b*64 + koff + ci]
        // warp reads 128B contiguous per dn (ci fast); STS 2-way conflict (AST=258)
        #pragma unroll
        for (int dn = 0; dn < 32; dn++) {
            int n = n0 + dn;
            if (n >= NN) n = NN - 1;               // clamp; stores are guarded
            As[s_ci * AST + dn * 8 + s_b] =
                __ldg(&src[(size_t)n * FF + s_b * 64 + koff + s_ci]);
        }
        __syncthreads();

        #pragma unroll 4
        for (int kk = 0; kk < KC; kk++) {
            // warp-uniform W broadcast: 8 cols
            const float4* wrow = (const float4*)(Ws + kk * 64 + wp * 8);
            float4 wa = wrow[0], wb = wrow[1];
            unsigned long long wd[8];
            wd[0] = pack2(wa.x); wd[1] = pack2(wa.y);
            wd[2] = pack2(wa.z); wd[3] = pack2(wa.w);
            wd[4] = pack2(wb.x); wd[5] = pack2(wb.y);
            wd[6] = pack2(wb.z); wd[7] = pack2(wb.w);
            #pragma unroll
            for (int jp = 0; jp < 4; jp++) {
                // row pair (m0, m0+1), m0 = jp*64 + 2*tx  (even, 8B-aligned)
                unsigned long long ap =
                    *(const unsigned long long*)(As + kk * AST + jp * 64 + 2 * tx);
                #pragma unroll
                for (int c = 0; c < 8; c++) FMA2(acc[jp][c], ap, wd[c]);
            }
        }
    }

    // epilogue: bias + store, rows guarded for the partial last block
    float bvs[8];
    {
        float4 b0 = *(const float4*)(bias + wp * 8);
        float4 b1 = *(const float4*)(bias + wp * 8 + 4);
        bvs[0]=b0.x; bvs[1]=b0.y; bvs[2]=b0.z; bvs[3]=b0.w;
        bvs[4]=b1.x; bvs[5]=b1.y; bvs[6]=b1.z; bvs[7]=b1.w;
    }
    #pragma unroll
    for (int jp = 0; jp < 4; jp++) {
        int m0 = jp * 64 + 2 * tx;       // pair shares dn; b and b+1
        int dn = m0 >> 3;
        int n  = n0 + dn;
        if (n >= NN) continue;
        int b  = m0 & 7;
        float lo[8], hi[8];
        #pragma unroll
        for (int c = 0; c < 8; c++) unpack2(acc[jp][c], lo[c], hi[c]);
        float4 o0, o1;
        o0.x = lo[0]+bvs[0]; o0.y = lo[1]+bvs[1]; o0.z = lo[2]+bvs[2]; o0.w = lo[3]+bvs[3];
        o1.x = lo[4]+bvs[4]; o1.y = lo[5]+bvs[5]; o1.z = lo[6]+bvs[6]; o1.w = lo[7]+bvs[7];
        float* p0 = out + ((size_t)b * NN + n) * 64 + wp * 8;
        *(float4*)p0 = o0; *(float4*)(p0 + 4) = o1;
        o0.x = hi[0]+bvs[0]; o0.y = hi[1]+bvs[1]; o0.z = hi[2]+bvs[2]; o0.w = hi[3]+bvs[3];
        o1.x = hi[4]+bvs[4]; o1.y = hi[5]+bvs[5]; o1.z = hi[6]+bvs[6]; o1.w = hi[7]+bvs[7];
        float* p1 = out + ((size_t)(b + 1) * NN + n) * 64 + wp * 8;
        *(float4*)p1 = o0; *(float4*)(p1 + 4) = o1;
    }
}

// ---------------- launch ----------------------------------------------------
extern "C" void kernel_launch(void* const* d_in, const int* in_sizes, int n_in,
                              void* d_out, int out_size) {
    const float* x    = (const float*)d_in[0];   // [8, 50000, 64] f32
    const float* wgt  = (const float*)d_in[1];   // [3, 64, 64]    f32
    const float* bias = (const float*)d_in[2];   // [64]           f32
    const void*  ei   = d_in[3];                 // [2, 400000] int64 or int32
    float* out = (float*)d_out;                  // [8, 50000, 64] f32

    k_init<<<(NN + 255) / 256, 256>>>();
    k_detect<<<1, 64>>>(ei);
    k_count<<<(EE + 255) / 256, 256>>>(ei);
    k_dinv<<<(NN + 255) / 256, 256>>>();
    k_assign<<<(NN + 255) / 256, 256>>>();
    k_fill<<<(EE + 255) / 256, 256>>>(ei);
    k_transpose<<<(NN * FF4 + 255) / 256, 256>>>(x);
    k_spmm<<<(NN * 32 + 255) / 256, 256>>>(0);
    k_spmm<<<(NN * 32 + 255) / 256, 256>>>(1);
    k_gemm2<<<(NN + 31) / 32, 256>>>(wgt, bias, out);
}